// round 14
// baseline (speedup 1.0000x reference)
#include <cuda_runtime.h>
#include <cuda_bf16.h>

#define NN   150000
#define EE   1200000
#define ACTD 6
#define BB   25000
#define GLB  256
#define GOUT 10
#define KIN  384
#define NSCAN_BLK 147   // ceil(NN/1024)
#define GLOB_BLKS 391   // ceil(BB/64)
#define GATH_BLKS 18750 // NN*32/256

typedef unsigned long long ull;

// ---------------- static device scratch ----------------
__device__ __align__(16) float g_h2[NN * 64];
__device__ __align__(16) float g_agg[NN * 64];
__device__ float g_dinv[NN];
__device__ int   g_cnt[NN];
__device__ int   g_off[NN + 1];
__device__ int   g_cur[NN];
__device__ int   g_csr[EE];
__device__ int   g_bsum[256];
__device__ int   g_boff[256];
__device__ __align__(8) int2 g_sd[EE];
__device__ int   g_is64;
__device__ __align__(16) __nv_bfloat16 g_Wh[GLB * KIN];
__device__ __align__(16) __nv_bfloat16 g_Wl[GLB * KIN];
__device__ __align__(16) __nv_bfloat16 g_CWh[64 * 64];
__device__ __align__(16) __nv_bfloat16 g_CWl[64 * 64];
__device__ __align__(16) __nv_bfloat16 g_Xh[BB * KIN];
__device__ __align__(16) __nv_bfloat16 g_Xl[BB * KIN];
__device__ float g_xg[BB * GOUT];
__device__ float g_conc[NN];
__device__ float g_sum;

// ---------------- helpers ----------------
__device__ __forceinline__ float leakyf(float x) { return x > 0.f ? x : 0.01f * x; }
__device__ __forceinline__ float softplusf(float x) {
    return fmaxf(x, 0.f) + log1pf(expf(-fabsf(x)));
}
__device__ __forceinline__ ull pk2(float x, float y) {
    ull r;
    asm("mov.b64 %0, {%1, %2};" : "=l"(r) : "f"(x), "f"(y));
    return r;
}
__device__ __forceinline__ void fma2(ull& d, ull a, ull b) {
    asm("fma.rn.f32x2 %0, %1, %2, %3;" : "=l"(d) : "l"(a), "l"(b), "l"(d));
}
__device__ __forceinline__ float2 up2(ull v) {
    float lo, hi;
    asm("mov.b64 {%0, %1}, %2;" : "=f"(lo), "=f"(hi) : "l"(v));
    return make_float2(lo, hi);
}
__device__ __forceinline__ void cpa16g(unsigned dst, const void* src) {
    asm volatile("cp.async.cg.shared.global [%0], [%1], 16;" ::"r"(dst), "l"(src));
}
__device__ __forceinline__ void cpa16z(unsigned dst, const void* src, int sz) {
    asm volatile("cp.async.cg.shared.global [%0], [%1], 16, %2;" ::"r"(dst), "l"(src), "r"(sz));
}
__device__ __forceinline__ void ldx4(unsigned* r, unsigned addr) {
    asm volatile("ldmatrix.sync.aligned.m8n8.x4.shared.b16 {%0,%1,%2,%3}, [%4];"
                 : "=r"(r[0]), "=r"(r[1]), "=r"(r[2]), "=r"(r[3])
                 : "r"(addr));
}
__device__ __forceinline__ void mma_bf16(float* c, const unsigned* a, unsigned b0, unsigned b1) {
    asm volatile(
        "mma.sync.aligned.m16n8k16.row.col.f32.bf16.bf16.f32 "
        "{%0,%1,%2,%3},{%4,%5,%6,%7},{%8,%9},{%0,%1,%2,%3};"
        : "+f"(c[0]), "+f"(c[1]), "+f"(c[2]), "+f"(c[3])
        : "r"(a[0]), "r"(a[1]), "r"(a[2]), "r"(a[3]), "r"(b0), "r"(b1));
}

// ---------------- setup kernels ----------------
__global__ void k_zero(const void* __restrict__ eidx) {
    int i = blockIdx.x * 256 + threadIdx.x;
    if (i < NN) g_cnt[i] = 0;
    if (i == 0) {
        g_sum = 0.f;
        const long long* p64 = (const long long*)eidx;
        int is64 = 1;
#pragma unroll
        for (int t = 0; t < 8; t++) {
            unsigned long long v = (unsigned long long)p64[t];
            if (v >= (unsigned long long)NN) is64 = 0;
        }
        g_is64 = is64;
    }
}

__global__ void k_edges(const void* __restrict__ eidx) {
    int e = blockIdx.x * 256 + threadIdx.x;
    if (e >= EE) return;
    int s, d;
    if (g_is64) {
        const long long* p64 = (const long long*)eidx;
        s = (int)p64[e];
        d = (int)p64[EE + e];
    } else {
        const int* p32 = (const int*)eidx;
        s = p32[e];
        d = p32[EE + e];
    }
    g_sd[e] = make_int2(s, d);
    atomicAdd(&g_cnt[d], 1);
}

// ---- CSR scan (dinv fused into bsum) ----
__global__ __launch_bounds__(1024) void k_bsum() {
    __shared__ int sred[32];
    int tid = threadIdx.x;
    int i = blockIdx.x * 1024 + tid;
    int v = 0;
    if (i < NN) {
        v = g_cnt[i];
        g_dinv[i] = rsqrtf((float)v + 1.0f);
    }
    int w = v;
#pragma unroll
    for (int off = 16; off; off >>= 1) w += __shfl_xor_sync(0xffffffffu, w, off);
    if ((tid & 31) == 0) sred[tid >> 5] = w;
    __syncthreads();
    if (tid < 32) {
        int x = sred[tid];
#pragma unroll
        for (int off = 16; off; off >>= 1) x += __shfl_xor_sync(0xffffffffu, x, off);
        if (tid == 0) g_bsum[blockIdx.x] = x;
    }
}

__global__ __launch_bounds__(256) void k_bscan() {
    __shared__ int s[256];
    int tid = threadIdx.x;
    int v = (tid < NSCAN_BLK) ? g_bsum[tid] : 0;
    s[tid] = v;
    __syncthreads();
#pragma unroll
    for (int off = 1; off < 256; off <<= 1) {
        int t = (tid >= off) ? s[tid - off] : 0;
        __syncthreads();
        s[tid] += t;
        __syncthreads();
    }
    g_boff[tid] = s[tid] - v;
    if (tid == 0) g_off[NN] = EE;
}

__global__ __launch_bounds__(1024) void k_off() {
    __shared__ int s[1024];
    int tid = threadIdx.x;
    int i = blockIdx.x * 1024 + tid;
    int v = (i < NN) ? g_cnt[i] : 0;
    s[tid] = v;
    __syncthreads();
#pragma unroll
    for (int off = 1; off < 1024; off <<= 1) {
        int t = (tid >= off) ? s[tid - off] : 0;
        __syncthreads();
        s[tid] += t;
        __syncthreads();
    }
    if (i < NN) {
        int excl = s[tid] - v + g_boff[blockIdx.x];
        g_off[i] = excl;
        g_cur[i] = excl;
    }
}

__global__ void k_fill() {
    int e = blockIdx.x * 256 + threadIdx.x;
    if (e >= EE) return;
    int2 sd = g_sd[e];
    int pos = atomicAdd(&g_cur[sd.y], 1);
    g_csr[pos] = sd.x;
}

// ---- merged bf16 hi/lo splits: convW, then gW1, then X ----
__global__ void k_wx(const float* __restrict__ gW1, const float* __restrict__ state,
                     const float* __restrict__ convW) {
    int t = blockIdx.x * 256 + threadIdx.x;
    if (t < 4096) {
        float w = convW[t];
        __nv_bfloat16 h = __float2bfloat16(w);
        g_CWh[t] = h;
        g_CWl[t] = __float2bfloat16(w - __bfloat162float(h));
        return;
    }
    if (t < 4096 + GLB * KIN) {
        int i = t - 4096;
        float w = gW1[i];
        __nv_bfloat16 h = __float2bfloat16(w);
        g_Wh[i] = h;
        g_Wl[i] = __float2bfloat16(w - __bfloat162float(h));
        return;
    }
    long long xt = (long long)(t - 4096 - GLB * KIN);
    long long i = xt * 8;
    if (i >= (long long)BB * KIN) return;
    float4 v0 = *(const float4*)&state[i];
    float4 v1 = *(const float4*)&state[i + 4];
    float xs[8] = {v0.x, v0.y, v0.z, v0.w, v1.x, v1.y, v1.z, v1.w};
    __align__(16) __nv_bfloat16 h[8], l[8];
#pragma unroll
    for (int q = 0; q < 8; q++) {
        h[q] = __float2bfloat16(xs[q]);
        l[q] = __float2bfloat16(xs[q] - __bfloat162float(h[q]));
    }
    *(uint4*)&g_Xh[i] = *(uint4*)h;
    *(uint4*)&g_Xl[i] = *(uint4*)l;
}

// ---------------- k_conv v2: tensor bf16x3, 128 rows/block ----------------
#define CV_AHI 0u
#define CV_ALO 18432u
#define CV_BHI 36864u
#define CV_BLO 46080u
#define CONV_SMEM 55296
__global__ __launch_bounds__(256) void k_conv() {
    extern __shared__ char smc[];
    unsigned smBase = (unsigned)__cvta_generic_to_shared(smc);
    int tid = threadIdx.x;
    int base = blockIdx.x * 128;

    for (int idx = tid; idx < 2048; idx += 256) {
        int p = idx >> 10;
        int rem = idx & 1023;
        int row = rem >> 3, seg = rem & 7;
        int node = base + row;
        const __nv_bfloat16* src = (p ? g_Xl : g_Xh) +
                                   (long long)(node < NN ? node : 0) * 64 + seg * 8;
        unsigned d = smBase + (p ? CV_ALO : CV_AHI) + (unsigned)(row * 144 + seg * 16);
        cpa16z(d, src, (node < NN) ? 16 : 0);
    }
    for (int idx = tid; idx < 1024; idx += 256) {
        int p = idx >> 9;
        int rem = idx & 511;
        int o = rem >> 3, seg = rem & 7;
        const __nv_bfloat16* src = (p ? g_CWl : g_CWh) + o * 64 + seg * 8;
        unsigned d = smBase + (p ? CV_BLO : CV_BHI) + (unsigned)(o * 144 + seg * 16);
        cpa16g(d, src);
    }
    asm volatile("cp.async.commit_group;");
    asm volatile("cp.async.wait_group 0;");
    __syncthreads();

    int warp = tid >> 5, lane = tid & 31;
    int wm = warp >> 1, wn = warp & 1;
    int g = lane >> 3;

    float C[2][4][4];
#pragma unroll
    for (int t = 0; t < 2; t++)
#pragma unroll
        for (int j = 0; j < 4; j++)
#pragma unroll
            for (int q = 0; q < 4; q++) C[t][j][q] = 0.f;

#pragma unroll
    for (int ks = 0; ks < 4; ks++) {
        unsigned ah[2][4], al[2][4];
#pragma unroll
        for (int t = 0; t < 2; t++) {
            unsigned sa = smBase + CV_AHI +
                          (unsigned)((wm * 32 + t * 16 + (lane & 15)) * 144 + ks * 32 +
                                     (lane >> 4) * 16);
            ldx4(ah[t], sa);
            ldx4(al[t], sa + (CV_ALO - CV_AHI));
        }
#pragma unroll
        for (int i = 0; i < 2; i++) {
            int ntile = wn * 4 + 2 * i + (g >> 1);
            unsigned bH = smBase + CV_BHI +
                          (unsigned)((ntile * 8 + (lane & 7)) * 144 + ks * 32 + (g & 1) * 16);
            unsigned bh[4], bl[4];
            ldx4(bh, bH);
            ldx4(bl, bH + (CV_BLO - CV_BHI));
#pragma unroll
            for (int t = 0; t < 2; t++) {
                mma_bf16(C[t][2 * i], ah[t], bh[0], bh[1]);
                mma_bf16(C[t][2 * i], ah[t], bl[0], bl[1]);
                mma_bf16(C[t][2 * i], al[t], bh[0], bh[1]);
                mma_bf16(C[t][2 * i + 1], ah[t], bh[2], bh[3]);
                mma_bf16(C[t][2 * i + 1], ah[t], bl[2], bl[3]);
                mma_bf16(C[t][2 * i + 1], al[t], bh[2], bh[3]);
            }
        }
    }

#pragma unroll
    for (int t = 0; t < 2; t++) {
        int r0 = base + wm * 32 + t * 16 + (lane >> 2);
        int r1 = r0 + 8;
        float d0 = (r0 < NN) ? g_dinv[r0] : 0.f;
        float d1 = (r1 < NN) ? g_dinv[r1] : 0.f;
#pragma unroll
        for (int j = 0; j < 4; j++) {
            int n = wn * 32 + j * 8 + (lane & 3) * 2;
            if (r0 < NN)
                *(float2*)&g_h2[r0 * 64 + n] = make_float2(C[t][j][0] * d0, C[t][j][1] * d0);
            if (r1 < NN)
                *(float2*)&g_h2[r1 * 64 + n] = make_float2(C[t][j][2] * d1, C[t][j][3] * d1);
        }
    }
}

// ---------------- device bodies for the fused mega kernel ----------------
__device__ void dev_gather(int bid) {
    int node = (bid * 256 + threadIdx.x) >> 5;
    if (node >= NN) return;
    int lane = threadIdx.x & 31;
    int c = lane * 2;

    float2 acc = *(const float2*)&g_h2[node * 64 + c];
    int j0 = g_off[node], j1 = g_off[node + 1];
    int j = j0;
    for (; j + 3 < j1; j += 4) {
        int s0 = g_csr[j], s1 = g_csr[j + 1], s2 = g_csr[j + 2], s3 = g_csr[j + 3];
        float2 v0 = *(const float2*)&g_h2[s0 * 64 + c];
        float2 v1 = *(const float2*)&g_h2[s1 * 64 + c];
        float2 v2 = *(const float2*)&g_h2[s2 * 64 + c];
        float2 v3 = *(const float2*)&g_h2[s3 * 64 + c];
        acc.x += v0.x + v1.x + v2.x + v3.x;
        acc.y += v0.y + v1.y + v2.y + v3.y;
    }
    for (; j < j1; j++) {
        int s = g_csr[j];
        float2 v = *(const float2*)&g_h2[s * 64 + c];
        acc.x += v.x;
        acc.y += v.y;
    }
    *(float2*)&g_agg[node * 64 + c] = acc;
}

// glob v6 body (R11/R13 best): 64 rows x 256 cols, 256 thr
#define GNC2 24
#define GB_SBL   12288u
#define GB_SBUF  24576u
#define GB_SA    49152u
#define GB_SAL   3072u
#define GB_SABUF 6144u
#define GB_B1OFF 67584
#define GLOB_SMEM (GB_B1OFF + 1024)
__device__ void dev_glob(int bid, const float* __restrict__ gb1,
                         const float* __restrict__ gW2, const float* __restrict__ gb2) {
    extern __shared__ char smc[];
    float* sb1 = (float*)(smc + GB_B1OFF);
    float* sH = (float*)smc;
    unsigned smBase = (unsigned)__cvta_generic_to_shared(smc);
    int tid = threadIdx.x;
    int base = bid * 64;
    sb1[tid] = gb1[tid];

    auto stage = [&](int ch) {
        unsigned sb = smBase + (unsigned)((ch & 1) * GB_SBUF) + (unsigned)(tid * 48);
        const __nv_bfloat16* wh = g_Wh + tid * KIN + ch * 16;
        const __nv_bfloat16* wl = g_Wl + tid * KIN + ch * 16;
        cpa16g(sb, wh);
        cpa16g(sb + 16, wh + 8);
        cpa16g(sb + GB_SBL, wl);
        cpa16g(sb + GB_SBL + 16, wl + 8);
        if (tid < 128) {
            int r = tid & 63;
            int row = base + r;
            const __nv_bfloat16* src = ((tid < 64) ? g_Xh : g_Xl) +
                                       (long long)(row < BB ? row : 0) * KIN + ch * 16;
            unsigned d = smBase + GB_SA + (unsigned)((ch & 1) * GB_SABUF) +
                         ((tid < 64) ? 0u : GB_SAL) + (unsigned)(r * 48);
            int sz = (row < BB) ? 16 : 0;
            cpa16z(d, src, sz);
            cpa16z(d + 16, src + 8, sz);
        }
        asm volatile("cp.async.commit_group;");
    };

    stage(0);
    stage(1);
    asm volatile("cp.async.wait_group 1;");
    __syncthreads();

    int warp = tid >> 5, lane = tid & 31;
    int wm = warp >> 2, wn = warp & 3;
    int g = lane >> 3;

    float C[2][8][4];
#pragma unroll
    for (int t = 0; t < 2; t++)
#pragma unroll
        for (int j = 0; j < 8; j++)
#pragma unroll
            for (int q = 0; q < 4; q++) C[t][j][q] = 0.f;

#pragma unroll 1
    for (int ch = 0; ch < GNC2; ch++) {
        unsigned abase = smBase + GB_SA + (unsigned)((ch & 1) * GB_SABUF);
        unsigned ah[2][4], al[2][4];
#pragma unroll
        for (int t = 0; t < 2; t++) {
            unsigned sa = abase + (unsigned)((wm * 32 + t * 16 + (lane & 15)) * 48) +
                          (unsigned)((lane >> 4) * 16);
            ldx4(ah[t], sa);
            ldx4(al[t], sa + GB_SAL);
        }
        unsigned sbb = smBase + (unsigned)((ch & 1) * GB_SBUF);
#pragma unroll
        for (int i = 0; i < 4; i++) {
            int ntile = wn * 8 + 2 * i + (g >> 1);
            unsigned bH = sbb + (unsigned)((ntile * 8 + (lane & 7)) * 48) + (unsigned)((g & 1) * 16);
            unsigned bh[4], bl[4];
            ldx4(bh, bH);
            ldx4(bl, bH + GB_SBL);
#pragma unroll
            for (int t = 0; t < 2; t++) {
                mma_bf16(C[t][2 * i], ah[t], bh[0], bh[1]);
                mma_bf16(C[t][2 * i], ah[t], bl[0], bl[1]);
                mma_bf16(C[t][2 * i], al[t], bh[0], bh[1]);
                mma_bf16(C[t][2 * i + 1], ah[t], bh[2], bh[3]);
                mma_bf16(C[t][2 * i + 1], ah[t], bl[2], bl[3]);
                mma_bf16(C[t][2 * i + 1], al[t], bh[2], bh[3]);
            }
        }
        if (ch + 1 < GNC2) {
            __syncthreads();
            if (ch + 2 < GNC2) {
                stage(ch + 2);
                asm volatile("cp.async.wait_group 1;");
            } else {
                asm volatile("cp.async.wait_group 0;");
            }
            __syncthreads();
        }
    }
    __syncthreads();

#pragma unroll
    for (int t = 0; t < 2; t++) {
#pragma unroll
        for (int j = 0; j < 8; j++) {
            int n = wn * 64 + j * 8 + (lane & 3) * 2;
            int r0 = wm * 32 + t * 16 + (lane >> 2);
            float2 h0, h1;
            h0.x = leakyf(C[t][j][0] + sb1[n]);
            h0.y = leakyf(C[t][j][1] + sb1[n + 1]);
            h1.x = leakyf(C[t][j][2] + sb1[n]);
            h1.y = leakyf(C[t][j][3] + sb1[n + 1]);
            *(float2*)&sH[r0 * 260 + n] = h0;
            *(float2*)&sH[(r0 + 8) * 260 + n] = h1;
        }
    }
    __syncthreads();

    for (int t = tid; t < 64 * GOUT; t += 256) {
        int r = t / GOUT, o = t - r * GOUT;
        float a = gb2[o];
        const float* hr = &sH[r * 260];
        const float* wr = &gW2[o * GLB];
#pragma unroll 8
        for (int j2 = 0; j2 < GLB; j2++) a += hr[j2] * wr[j2];
        int b = base + r;
        if (b < BB) g_xg[b * GOUT + o] = leakyf(a);
    }
}

// ---------------- k_mega: glob blocks first, gather blocks backfill ----------------
__global__ __launch_bounds__(256) void k_mega(const float* __restrict__ gb1,
                                              const float* __restrict__ gW2,
                                              const float* __restrict__ gb2) {
    if (blockIdx.x < GLOB_BLKS)
        dev_glob(blockIdx.x, gb1, gW2, gb2);
    else
        dev_gather(blockIdx.x - GLOB_BLKS);
}

// ---------------- k_mlp (R6 best: 128 threads, 4x8 tile) ----------------
#define MLP_SX  0                   // [74][132]
#define MLP_SH  (74 * 132)          // [32][132]
#define MLP_SW1 (MLP_SH + 32 * 132) // [74][32]
#define MLP_SW2 (MLP_SW1 + 74 * 32) // [32][32]
#define MLP_SCB (MLP_SW2 + 32 * 32) // [64]
#define MLP_SB1 (MLP_SCB + 64)      // [32]
#define MLP_SB2 (MLP_SB1 + 32)      // [32]
#define MLP_SW3 (MLP_SB2 + 32)      // [32]
#define MLP_SB3 (MLP_SW3 + 32)      // [1]
#define MLP_SMEM ((MLP_SB3 + 4) * 4)
__global__ __launch_bounds__(128) void k_mlp(const float* __restrict__ state,
                                             const float* __restrict__ convb,
                                             const float* __restrict__ l1W,
                                             const float* __restrict__ l1b,
                                             const float* __restrict__ l2W,
                                             const float* __restrict__ l2b,
                                             const float* __restrict__ l3W,
                                             const float* __restrict__ l3b) {
    extern __shared__ float sm[];
    float* sX = sm + MLP_SX;
    float* sH = sm + MLP_SH;
    float* sW1 = sm + MLP_SW1;
    float* sW2 = sm + MLP_SW2;
    float* scb = sm + MLP_SCB;
    float* sb1 = sm + MLP_SB1;
    float* sb2 = sm + MLP_SB2;
    float* sw3 = sm + MLP_SW3;
    float* sb3 = sm + MLP_SB3;

    int tid = threadIdx.x;
    int base = blockIdx.x * 128;

    if (tid < 64) scb[tid] = convb[tid];
    if (tid < 32) {
        sb1[tid] = l1b[tid];
        sb2[tid] = l2b[tid];
        sw3[tid] = l3W[tid];
    }
    if (tid == 0) sb3[0] = l3b[0];
    for (int idx = tid; idx < 74 * 32; idx += 128) {
        int j = idx / 74, k = idx - j * 74;
        sW1[k * 32 + j] = l1W[idx];
    }
    for (int idx = tid; idx < 32 * 32; idx += 128) {
        int j = idx >> 5, k = idx & 31;
        sW2[k * 32 + j] = l2W[idx];
    }
    __syncthreads();

    for (int idx = tid; idx < 2048; idx += 128) {
        int r = idx >> 4, kq = (idx & 15) << 2;
        int row = base + r;
        float4 v = make_float4(0.f, 0.f, 0.f, 0.f);
        if (row < NN) {
            float di = g_dinv[row];
            float4 a = *(const float4*)&g_agg[row * 64 + kq];
            float4 s = *(const float4*)&state[row * 64 + kq];
            v.x = fmaxf(a.x * di + scb[kq + 0], 0.f) + s.x;
            v.y = fmaxf(a.y * di + scb[kq + 1], 0.f) + s.y;
            v.z = fmaxf(a.z * di + scb[kq + 2], 0.f) + s.z;
            v.w = fmaxf(a.w * di + scb[kq + 3], 0.f) + s.w;
        }
        sX[(kq + 0) * 132 + r] = v.x;
        sX[(kq + 1) * 132 + r] = v.y;
        sX[(kq + 2) * 132 + r] = v.z;
        sX[(kq + 3) * 132 + r] = v.w;
    }
    for (int idx = tid; idx < 128 * 10; idx += 128) {
        int r = idx / 10, k = idx - r * 10;
        int row = base + r;
        sX[(64 + k) * 132 + r] = (row < NN) ? g_xg[(row / ACTD) * 10 + k] : 0.f;
    }
    __syncthreads();

    int warp = tid >> 5, lane = tid & 31;
    int rg = lane >> 2, cg = lane & 3;
    int rowb = warp * 32 + rg * 4;
    int colb = cg * 8;

    ull acc[4][4];
#pragma unroll
    for (int r = 0; r < 4; r++)
#pragma unroll
        for (int c = 0; c < 4; c++) acc[r][c] = 0ull;
#pragma unroll 2
    for (int k = 0; k < 74; k++) {
        float4 xv = *(const float4*)&sX[k * 132 + rowb];
        ull xp[4] = {pk2(xv.x, xv.x), pk2(xv.y, xv.y), pk2(xv.z, xv.z), pk2(xv.w, xv.w)};
        const ulonglong2* wp = (const ulonglong2*)&sW1[k * 32 + colb];
        ulonglong2 wa = wp[0], wb = wp[1];
#pragma unroll
        for (int r = 0; r < 4; r++) {
            fma2(acc[r][0], xp[r], wa.x);
            fma2(acc[r][1], xp[r], wa.y);
            fma2(acc[r][2], xp[r], wb.x);
            fma2(acc[r][3], xp[r], wb.y);
        }
    }
    {
        float hv[4][8];
#pragma unroll
        for (int r = 0; r < 4; r++)
#pragma unroll
            for (int cp = 0; cp < 4; cp++) {
                float2 v = up2(acc[r][cp]);
                int c = colb + cp * 2;
                hv[r][cp * 2] = leakyf(v.x + sb1[c]);
                hv[r][cp * 2 + 1] = leakyf(v.y + sb1[c + 1]);
            }
#pragma unroll
        for (int c = 0; c < 8; c++) {
            float4 f = make_float4(hv[0][c], hv[1][c], hv[2][c], hv[3][c]);
            *(float4*)&sH[(colb + c) * 132 + rowb] = f;
        }
    }
    __syncthreads();

#pragma unroll
    for (int r = 0; r < 4; r++)
#pragma unroll
        for (int c = 0; c < 4; c++) acc[r][c] = 0ull;
#pragma unroll 4
    for (int k = 0; k < 32; k++) {
        float4 xv = *(const float4*)&sH[k * 132 + rowb];
        ull xp[4] = {pk2(xv.x, xv.x), pk2(xv.y, xv.y), pk2(xv.z, xv.z), pk2(xv.w, xv.w)};
        const ulonglong2* wp = (const ulonglong2*)&sW2[k * 32 + colb];
        ulonglong2 wa = wp[0], wb = wp[1];
#pragma unroll
        for (int r = 0; r < 4; r++) {
            fma2(acc[r][0], xp[r], wa.x);
            fma2(acc[r][1], xp[r], wa.y);
            fma2(acc[r][2], xp[r], wb.x);
            fma2(acc[r][3], xp[r], wb.y);
        }
    }

    float srow[4];
#pragma unroll
    for (int r = 0; r < 4; r++) {
        float s = 0.f;
#pragma unroll
        for (int cp = 0; cp < 4; cp++) {
            float2 v = up2(acc[r][cp]);
            int c = colb + cp * 2;
            float h0 = leakyf(v.x + sb2[c]);
            float h1 = leakyf(v.y + sb2[c + 1]);
            s += h0 * sw3[c] + h1 * sw3[c + 1];
        }
        srow[r] = s;
    }
#pragma unroll
    for (int r = 0; r < 4; r++) {
        srow[r] += __shfl_xor_sync(0xffffffffu, srow[r], 1);
        srow[r] += __shfl_xor_sync(0xffffffffu, srow[r], 2);
    }
    float lsum = 0.f;
    if (cg == 0) {
        float b3 = sb3[0];
#pragma unroll
        for (int r = 0; r < 4; r++) {
            int node = base + rowb + r;
            if (node < NN) {
                float conc = softplusf(srow[r] + b3);
                g_conc[node] = conc;
                lsum += conc;
            }
        }
    }
#pragma unroll
    for (int off = 16; off; off >>= 1) lsum += __shfl_xor_sync(0xffffffffu, lsum, off);
    if (lane == 0) atomicAdd(&g_sum, lsum);
}

// ---------------- finalize ----------------
__global__ void k_final(float* __restrict__ out, int writeReg) {
    int b = blockIdx.x * 256 + threadIdx.x;
    if (b == 0 && writeReg) out[NN] = g_sum * (1.0f / (float)NN);
    if (b >= BB) return;
    float c[ACTD];
    float s = 0.f;
#pragma unroll
    for (int a = 0; a < ACTD; a++) {
        c[a] = g_conc[b * ACTD + a];
        s += c[a];
    }
    float inv = 1.f / (s + 1e-20f);
#pragma unroll
    for (int a = 0; a < ACTD; a++) out[b * ACTD + a] = c[a] * inv;
}

// ---------------- launch ----------------
extern "C" void kernel_launch(void* const* d_in, const int* in_sizes, int n_in,
                              void* d_out, int out_size) {
    const float* state = (const float*)d_in[0];
    const void*  eidx  = d_in[1];
    const float* convW = (const float*)d_in[2];
    const float* convb = (const float*)d_in[3];
    const float* gW1   = (const float*)d_in[4];
    const float* gb1   = (const float*)d_in[5];
    const float* gW2   = (const float*)d_in[6];
    const float* gb2   = (const float*)d_in[7];
    const float* l1W   = (const float*)d_in[8];
    const float* l1b   = (const float*)d_in[9];
    const float* l2W   = (const float*)d_in[10];
    const float* l2b   = (const float*)d_in[11];
    const float* l3W   = (const float*)d_in[12];
    const float* l3b   = (const float*)d_in[13];
    float* out = (float*)d_out;

    cudaFuncSetAttribute(k_conv, cudaFuncAttributeMaxDynamicSharedMemorySize, CONV_SMEM);
    cudaFuncSetAttribute(k_mega, cudaFuncAttributeMaxDynamicSharedMemorySize, GLOB_SMEM);
    cudaFuncSetAttribute(k_mlp,  cudaFuncAttributeMaxDynamicSharedMemorySize, MLP_SMEM);

    k_wx<<<(4096 + GLB * KIN + BB * KIN / 8 + 255) / 256, 256>>>(gW1, state, convW);
    k_zero<<<(NN + 255) / 256, 256>>>(eidx);
    k_edges<<<(EE + 255) / 256, 256>>>(eidx);
    k_bsum<<<NSCAN_BLK, 1024>>>();
    k_bscan<<<1, 256>>>();
    k_off<<<NSCAN_BLK, 1024>>>();
    k_fill<<<(EE + 255) / 256, 256>>>();
    k_conv<<<(NN + 127) / 128, 256, CONV_SMEM>>>();
    k_mega<<<GLOB_BLKS + GATH_BLKS, 256, GLOB_SMEM>>>(gb1, gW2, gb2);
    k_mlp<<<(NN + 127) / 128, 128, MLP_SMEM>>>(state, convb, l1W, l1b, l2W, l2b, l3W, l3b);
    k_final<<<(BB + 255) / 256, 256>>>(out, out_size > NN ? 1 : 0);
}

// round 15
// speedup vs baseline: 1.2148x; 1.2148x over previous
#include <cuda_runtime.h>
#include <cuda_bf16.h>

#define NN   150000
#define EE   1200000
#define ACTD 6
#define BB   25000
#define GLB  256
#define GOUT 10
#define KIN  384
#define NSCAN_BLK 147   // ceil(NN/1024)
#define GLOB_BLKS 391   // ceil(BB/64)
#define CONV_BLKS 1172  // ceil(NN/128)

typedef unsigned long long ull;

// ---------------- static device scratch ----------------
__device__ __align__(16) float g_h2[NN * 64];
__device__ __align__(16) float g_agg[NN * 64];
__device__ float g_dinv[NN];
__device__ int   g_cnt[NN];
__device__ int   g_off[NN + 1];
__device__ int   g_cur[NN];
__device__ int   g_csr[EE];
__device__ int   g_bsum[256];
__device__ int   g_boff[256];
__device__ __align__(8) int2 g_sd[EE];
__device__ int   g_is64;
__device__ __align__(16) __nv_bfloat16 g_Wh[GLB * KIN];
__device__ __align__(16) __nv_bfloat16 g_Wl[GLB * KIN];
__device__ __align__(16) __nv_bfloat16 g_CWh[64 * 64];
__device__ __align__(16) __nv_bfloat16 g_CWl[64 * 64];
__device__ __align__(16) __nv_bfloat16 g_Xh[BB * KIN];
__device__ __align__(16) __nv_bfloat16 g_Xl[BB * KIN];
__device__ float g_xg[BB * GOUT];
__device__ float g_conc[NN];
__device__ float g_sum;

// ---------------- helpers ----------------
__device__ __forceinline__ float leakyf(float x) { return x > 0.f ? x : 0.01f * x; }
__device__ __forceinline__ float softplusf(float x) {
    return fmaxf(x, 0.f) + log1pf(expf(-fabsf(x)));
}
__device__ __forceinline__ ull pk2(float x, float y) {
    ull r;
    asm("mov.b64 %0, {%1, %2};" : "=l"(r) : "f"(x), "f"(y));
    return r;
}
__device__ __forceinline__ void fma2(ull& d, ull a, ull b) {
    asm("fma.rn.f32x2 %0, %1, %2, %3;" : "=l"(d) : "l"(a), "l"(b), "l"(d));
}
__device__ __forceinline__ float2 up2(ull v) {
    float lo, hi;
    asm("mov.b64 {%0, %1}, %2;" : "=f"(lo), "=f"(hi) : "l"(v));
    return make_float2(lo, hi);
}
__device__ __forceinline__ void cpa16g(unsigned dst, const void* src) {
    asm volatile("cp.async.cg.shared.global [%0], [%1], 16;" ::"r"(dst), "l"(src));
}
__device__ __forceinline__ void cpa16z(unsigned dst, const void* src, int sz) {
    asm volatile("cp.async.cg.shared.global [%0], [%1], 16, %2;" ::"r"(dst), "l"(src), "r"(sz));
}
__device__ __forceinline__ void ldx4(unsigned* r, unsigned addr) {
    asm volatile("ldmatrix.sync.aligned.m8n8.x4.shared.b16 {%0,%1,%2,%3}, [%4];"
                 : "=r"(r[0]), "=r"(r[1]), "=r"(r[2]), "=r"(r[3])
                 : "r"(addr));
}
__device__ __forceinline__ void mma_bf16(float* c, const unsigned* a, unsigned b0, unsigned b1) {
    asm volatile(
        "mma.sync.aligned.m16n8k16.row.col.f32.bf16.bf16.f32 "
        "{%0,%1,%2,%3},{%4,%5,%6,%7},{%8,%9},{%0,%1,%2,%3};"
        : "+f"(c[0]), "+f"(c[1]), "+f"(c[2]), "+f"(c[3])
        : "r"(a[0]), "r"(a[1]), "r"(a[2]), "r"(a[3]), "r"(b0), "r"(b1));
}

// ---------------- setup kernels ----------------
__global__ void k_zero(const void* __restrict__ eidx) {
    int i = blockIdx.x * 256 + threadIdx.x;
    if (i < NN) g_cnt[i] = 0;
    if (i == 0) {
        g_sum = 0.f;
        const long long* p64 = (const long long*)eidx;
        int is64 = 1;
#pragma unroll
        for (int t = 0; t < 8; t++) {
            unsigned long long v = (unsigned long long)p64[t];
            if (v >= (unsigned long long)NN) is64 = 0;
        }
        g_is64 = is64;
    }
}

__global__ void k_edges(const void* __restrict__ eidx) {
    int e = blockIdx.x * 256 + threadIdx.x;
    if (e >= EE) return;
    int s, d;
    if (g_is64) {
        const long long* p64 = (const long long*)eidx;
        s = (int)p64[e];
        d = (int)p64[EE + e];
    } else {
        const int* p32 = (const int*)eidx;
        s = p32[e];
        d = p32[EE + e];
    }
    g_sd[e] = make_int2(s, d);
    atomicAdd(&g_cnt[d], 1);
}

// ---- CSR scan (dinv fused into bsum) ----
__global__ __launch_bounds__(1024) void k_bsum() {
    __shared__ int sred[32];
    int tid = threadIdx.x;
    int i = blockIdx.x * 1024 + tid;
    int v = 0;
    if (i < NN) {
        v = g_cnt[i];
        g_dinv[i] = rsqrtf((float)v + 1.0f);
    }
    int w = v;
#pragma unroll
    for (int off = 16; off; off >>= 1) w += __shfl_xor_sync(0xffffffffu, w, off);
    if ((tid & 31) == 0) sred[tid >> 5] = w;
    __syncthreads();
    if (tid < 32) {
        int x = sred[tid];
#pragma unroll
        for (int off = 16; off; off >>= 1) x += __shfl_xor_sync(0xffffffffu, x, off);
        if (tid == 0) g_bsum[blockIdx.x] = x;
    }
}

__global__ __launch_bounds__(256) void k_bscan() {
    __shared__ int s[256];
    int tid = threadIdx.x;
    int v = (tid < NSCAN_BLK) ? g_bsum[tid] : 0;
    s[tid] = v;
    __syncthreads();
#pragma unroll
    for (int off = 1; off < 256; off <<= 1) {
        int t = (tid >= off) ? s[tid - off] : 0;
        __syncthreads();
        s[tid] += t;
        __syncthreads();
    }
    g_boff[tid] = s[tid] - v;
    if (tid == 0) g_off[NN] = EE;
}

__global__ __launch_bounds__(1024) void k_off() {
    __shared__ int s[1024];
    int tid = threadIdx.x;
    int i = blockIdx.x * 1024 + tid;
    int v = (i < NN) ? g_cnt[i] : 0;
    s[tid] = v;
    __syncthreads();
#pragma unroll
    for (int off = 1; off < 1024; off <<= 1) {
        int t = (tid >= off) ? s[tid - off] : 0;
        __syncthreads();
        s[tid] += t;
        __syncthreads();
    }
    if (i < NN) {
        int excl = s[tid] - v + g_boff[blockIdx.x];
        g_off[i] = excl;
        g_cur[i] = excl;
    }
}

__global__ void k_fill() {
    int e = blockIdx.x * 256 + threadIdx.x;
    if (e >= EE) return;
    int2 sd = g_sd[e];
    int pos = atomicAdd(&g_cur[sd.y], 1);
    g_csr[pos] = sd.x;
}

// ---- merged bf16 hi/lo splits: convW, then gW1, then X ----
__global__ void k_wx(const float* __restrict__ gW1, const float* __restrict__ state,
                     const float* __restrict__ convW) {
    int t = blockIdx.x * 256 + threadIdx.x;
    if (t < 4096) {
        float w = convW[t];
        __nv_bfloat16 h = __float2bfloat16(w);
        g_CWh[t] = h;
        g_CWl[t] = __float2bfloat16(w - __bfloat162float(h));
        return;
    }
    if (t < 4096 + GLB * KIN) {
        int i = t - 4096;
        float w = gW1[i];
        __nv_bfloat16 h = __float2bfloat16(w);
        g_Wh[i] = h;
        g_Wl[i] = __float2bfloat16(w - __bfloat162float(h));
        return;
    }
    long long xt = (long long)(t - 4096 - GLB * KIN);
    long long i = xt * 8;
    if (i >= (long long)BB * KIN) return;
    float4 v0 = *(const float4*)&state[i];
    float4 v1 = *(const float4*)&state[i + 4];
    float xs[8] = {v0.x, v0.y, v0.z, v0.w, v1.x, v1.y, v1.z, v1.w};
    __align__(16) __nv_bfloat16 h[8], l[8];
#pragma unroll
    for (int q = 0; q < 8; q++) {
        h[q] = __float2bfloat16(xs[q]);
        l[q] = __float2bfloat16(xs[q] - __bfloat162float(h[q]));
    }
    *(uint4*)&g_Xh[i] = *(uint4*)h;
    *(uint4*)&g_Xl[i] = *(uint4*)l;
}

// ---------------- conv device body (tensor bf16x3, 128 rows/block) ----------------
#define CV_AHI 0u
#define CV_ALO 18432u
#define CV_BHI 36864u
#define CV_BLO 46080u
__device__ void dev_conv(int bid) {
    extern __shared__ char smc[];
    unsigned smBase = (unsigned)__cvta_generic_to_shared(smc);
    int tid = threadIdx.x;
    int base = bid * 128;

    for (int idx = tid; idx < 2048; idx += 256) {
        int p = idx >> 10;
        int rem = idx & 1023;
        int row = rem >> 3, seg = rem & 7;
        int node = base + row;
        const __nv_bfloat16* src = (p ? g_Xl : g_Xh) +
                                   (long long)(node < NN ? node : 0) * 64 + seg * 8;
        unsigned d = smBase + (p ? CV_ALO : CV_AHI) + (unsigned)(row * 144 + seg * 16);
        cpa16z(d, src, (node < NN) ? 16 : 0);
    }
    for (int idx = tid; idx < 1024; idx += 256) {
        int p = idx >> 9;
        int rem = idx & 511;
        int o = rem >> 3, seg = rem & 7;
        const __nv_bfloat16* src = (p ? g_CWl : g_CWh) + o * 64 + seg * 8;
        unsigned d = smBase + (p ? CV_BLO : CV_BHI) + (unsigned)(o * 144 + seg * 16);
        cpa16g(d, src);
    }
    asm volatile("cp.async.commit_group;");
    asm volatile("cp.async.wait_group 0;");
    __syncthreads();

    int warp = tid >> 5, lane = tid & 31;
    int wm = warp >> 1, wn = warp & 1;
    int g = lane >> 3;

    float C[2][4][4];
#pragma unroll
    for (int t = 0; t < 2; t++)
#pragma unroll
        for (int j = 0; j < 4; j++)
#pragma unroll
            for (int q = 0; q < 4; q++) C[t][j][q] = 0.f;

#pragma unroll
    for (int ks = 0; ks < 4; ks++) {
        unsigned ah[2][4], al[2][4];
#pragma unroll
        for (int t = 0; t < 2; t++) {
            unsigned sa = smBase + CV_AHI +
                          (unsigned)((wm * 32 + t * 16 + (lane & 15)) * 144 + ks * 32 +
                                     (lane >> 4) * 16);
            ldx4(ah[t], sa);
            ldx4(al[t], sa + (CV_ALO - CV_AHI));
        }
#pragma unroll
        for (int i = 0; i < 2; i++) {
            int ntile = wn * 4 + 2 * i + (g >> 1);
            unsigned bH = smBase + CV_BHI +
                          (unsigned)((ntile * 8 + (lane & 7)) * 144 + ks * 32 + (g & 1) * 16);
            unsigned bh[4], bl[4];
            ldx4(bh, bH);
            ldx4(bl, bH + (CV_BLO - CV_BHI));
#pragma unroll
            for (int t = 0; t < 2; t++) {
                mma_bf16(C[t][2 * i], ah[t], bh[0], bh[1]);
                mma_bf16(C[t][2 * i], ah[t], bl[0], bl[1]);
                mma_bf16(C[t][2 * i], al[t], bh[0], bh[1]);
                mma_bf16(C[t][2 * i + 1], ah[t], bh[2], bh[3]);
                mma_bf16(C[t][2 * i + 1], ah[t], bl[2], bl[3]);
                mma_bf16(C[t][2 * i + 1], al[t], bh[2], bh[3]);
            }
        }
    }

#pragma unroll
    for (int t = 0; t < 2; t++) {
        int r0 = base + wm * 32 + t * 16 + (lane >> 2);
        int r1 = r0 + 8;
        float d0 = (r0 < NN) ? g_dinv[r0] : 0.f;
        float d1 = (r1 < NN) ? g_dinv[r1] : 0.f;
#pragma unroll
        for (int j = 0; j < 4; j++) {
            int n = wn * 32 + j * 8 + (lane & 3) * 2;
            if (r0 < NN)
                *(float2*)&g_h2[r0 * 64 + n] = make_float2(C[t][j][0] * d0, C[t][j][1] * d0);
            if (r1 < NN)
                *(float2*)&g_h2[r1 * 64 + n] = make_float2(C[t][j][2] * d1, C[t][j][3] * d1);
        }
    }
}

// ---------------- glob device body: 3-buffer single-sync pipeline ----------------
#define GNC2 24
#define G3_BL   12288u    // lo offset within a B buffer
#define G3_BBUF 24576u    // one B buffer (hi+lo)
#define G3_A0   73728u    // A region start (3 B buffers before it)
#define G3_AL   3072u     // lo offset within an A buffer
#define G3_ABUF 6144u     // one A buffer (hi+lo)
#define G3_B1   92160     // sb1 (after 3 A buffers)
#define G3_SMEM (G3_B1 + 1024)
__device__ void dev_glob(int bid, const float* __restrict__ gb1,
                         const float* __restrict__ gW2, const float* __restrict__ gb2) {
    extern __shared__ char smc[];
    float* sb1 = (float*)(smc + G3_B1);
    float* sH = (float*)smc;
    unsigned smBase = (unsigned)__cvta_generic_to_shared(smc);
    int tid = threadIdx.x;
    int base = bid * 64;
    sb1[tid] = gb1[tid];

    auto stage = [&](int ch) {
        int buf = ch % 3;
        unsigned sb = smBase + (unsigned)(buf * G3_BBUF) + (unsigned)(tid * 48);
        const __nv_bfloat16* wh = g_Wh + tid * KIN + ch * 16;
        const __nv_bfloat16* wl = g_Wl + tid * KIN + ch * 16;
        cpa16g(sb, wh);
        cpa16g(sb + 16, wh + 8);
        cpa16g(sb + G3_BL, wl);
        cpa16g(sb + G3_BL + 16, wl + 8);
        if (tid < 128) {
            int r = tid & 63;
            int row = base + r;
            const __nv_bfloat16* src = ((tid < 64) ? g_Xh : g_Xl) +
                                       (long long)(row < BB ? row : 0) * KIN + ch * 16;
            unsigned d = smBase + G3_A0 + (unsigned)(buf * G3_ABUF) +
                         ((tid < 64) ? 0u : G3_AL) + (unsigned)(r * 48);
            int sz = (row < BB) ? 16 : 0;
            cpa16z(d, src, sz);
            cpa16z(d + 16, src + 8, sz);
        }
        asm volatile("cp.async.commit_group;");
    };

    stage(0);
    stage(1);

    int warp = tid >> 5, lane = tid & 31;
    int wm = warp >> 2, wn = warp & 3;
    int g = lane >> 3;

    float C[2][8][4];
#pragma unroll
    for (int t = 0; t < 2; t++)
#pragma unroll
        for (int j = 0; j < 8; j++)
#pragma unroll
            for (int q = 0; q < 4; q++) C[t][j][q] = 0.f;

#pragma unroll 1
    for (int ch = 0; ch < GNC2; ch++) {
        asm volatile("cp.async.wait_group 1;");
        __syncthreads();
        if (ch + 2 < GNC2) stage(ch + 2);

        int buf = ch % 3;
        unsigned abase = smBase + G3_A0 + (unsigned)(buf * G3_ABUF);
        unsigned ah[2][4], al[2][4];
#pragma unroll
        for (int t = 0; t < 2; t++) {
            unsigned sa = abase + (unsigned)((wm * 32 + t * 16 + (lane & 15)) * 48) +
                          (unsigned)((lane >> 4) * 16);
            ldx4(ah[t], sa);
            ldx4(al[t], sa + G3_AL);
        }
        unsigned sbb = smBase + (unsigned)(buf * G3_BBUF);
#pragma unroll
        for (int i = 0; i < 4; i++) {
            int ntile = wn * 8 + 2 * i + (g >> 1);
            unsigned bH = sbb + (unsigned)((ntile * 8 + (lane & 7)) * 48) + (unsigned)((g & 1) * 16);
            unsigned bh[4], bl[4];
            ldx4(bh, bH);
            ldx4(bl, bH + G3_BL);
#pragma unroll
            for (int t = 0; t < 2; t++) {
                mma_bf16(C[t][2 * i], ah[t], bh[0], bh[1]);
                mma_bf16(C[t][2 * i], ah[t], bl[0], bl[1]);
                mma_bf16(C[t][2 * i], al[t], bh[0], bh[1]);
                mma_bf16(C[t][2 * i + 1], ah[t], bh[2], bh[3]);
                mma_bf16(C[t][2 * i + 1], ah[t], bl[2], bl[3]);
                mma_bf16(C[t][2 * i + 1], al[t], bh[2], bh[3]);
            }
        }
    }
    asm volatile("cp.async.wait_group 0;");
    __syncthreads();

    // H = leaky(C + b1) into overlay [64][260]
#pragma unroll
    for (int t = 0; t < 2; t++) {
#pragma unroll
        for (int j = 0; j < 8; j++) {
            int n = wn * 64 + j * 8 + (lane & 3) * 2;
            int r0 = wm * 32 + t * 16 + (lane >> 2);
            float2 h0, h1;
            h0.x = leakyf(C[t][j][0] + sb1[n]);
            h0.y = leakyf(C[t][j][1] + sb1[n + 1]);
            h1.x = leakyf(C[t][j][2] + sb1[n]);
            h1.y = leakyf(C[t][j][3] + sb1[n + 1]);
            *(float2*)&sH[r0 * 260 + n] = h0;
            *(float2*)&sH[(r0 + 8) * 260 + n] = h1;
        }
    }
    __syncthreads();

    // layer 2: [64 x 256] @ gW2^T[256 x 10]
    for (int t = tid; t < 64 * GOUT; t += 256) {
        int r = t / GOUT, o = t - r * GOUT;
        float a = gb2[o];
        const float* hr = &sH[r * 260];
        const float* wr = &gW2[o * GLB];
#pragma unroll 8
        for (int j2 = 0; j2 < GLB; j2++) a += hr[j2] * wr[j2];
        int b = base + r;
        if (b < BB) g_xg[b * GOUT + o] = leakyf(a);
    }
}

// ---------------- k_mega2: glob blocks first, conv blocks backfill ----------------
__global__ __launch_bounds__(256) void k_mega2(const float* __restrict__ gb1,
                                               const float* __restrict__ gW2,
                                               const float* __restrict__ gb2) {
    if (blockIdx.x < GLOB_BLKS)
        dev_glob(blockIdx.x, gb1, gW2, gb2);
    else
        dev_conv(blockIdx.x - GLOB_BLKS);
}

// ---------------- k_gather (standalone, full occupancy) ----------------
__global__ __launch_bounds__(256) void k_gather() {
    int node = (blockIdx.x * 256 + threadIdx.x) >> 5;
    if (node >= NN) return;
    int lane = threadIdx.x & 31;
    int c = lane * 2;

    float2 acc = *(const float2*)&g_h2[node * 64 + c];
    int j0 = g_off[node], j1 = g_off[node + 1];
    int j = j0;
    for (; j + 3 < j1; j += 4) {
        int s0 = g_csr[j], s1 = g_csr[j + 1], s2 = g_csr[j + 2], s3 = g_csr[j + 3];
        float2 v0 = *(const float2*)&g_h2[s0 * 64 + c];
        float2 v1 = *(const float2*)&g_h2[s1 * 64 + c];
        float2 v2 = *(const float2*)&g_h2[s2 * 64 + c];
        float2 v3 = *(const float2*)&g_h2[s3 * 64 + c];
        acc.x += v0.x + v1.x + v2.x + v3.x;
        acc.y += v0.y + v1.y + v2.y + v3.y;
    }
    for (; j < j1; j++) {
        int s = g_csr[j];
        float2 v = *(const float2*)&g_h2[s * 64 + c];
        acc.x += v.x;
        acc.y += v.y;
    }
    *(float2*)&g_agg[node * 64 + c] = acc;
}

// ---------------- k_mlp (R6 best: 128 threads, 4x8 tile) ----------------
#define MLP_SX  0                   // [74][132]
#define MLP_SH  (74 * 132)          // [32][132]
#define MLP_SW1 (MLP_SH + 32 * 132) // [74][32]
#define MLP_SW2 (MLP_SW1 + 74 * 32) // [32][32]
#define MLP_SCB (MLP_SW2 + 32 * 32) // [64]
#define MLP_SB1 (MLP_SCB + 64)      // [32]
#define MLP_SB2 (MLP_SB1 + 32)      // [32]
#define MLP_SW3 (MLP_SB2 + 32)      // [32]
#define MLP_SB3 (MLP_SW3 + 32)      // [1]
#define MLP_SMEM ((MLP_SB3 + 4) * 4)
__global__ __launch_bounds__(128) void k_mlp(const float* __restrict__ state,
                                             const float* __restrict__ convb,
                                             const float* __restrict__ l1W,
                                             const float* __restrict__ l1b,
                                             const float* __restrict__ l2W,
                                             const float* __restrict__ l2b,
                                             const float* __restrict__ l3W,
                                             const float* __restrict__ l3b) {
    extern __shared__ float sm[];
    float* sX = sm + MLP_SX;
    float* sH = sm + MLP_SH;
    float* sW1 = sm + MLP_SW1;
    float* sW2 = sm + MLP_SW2;
    float* scb = sm + MLP_SCB;
    float* sb1 = sm + MLP_SB1;
    float* sb2 = sm + MLP_SB2;
    float* sw3 = sm + MLP_SW3;
    float* sb3 = sm + MLP_SB3;

    int tid = threadIdx.x;
    int base = blockIdx.x * 128;

    if (tid < 64) scb[tid] = convb[tid];
    if (tid < 32) {
        sb1[tid] = l1b[tid];
        sb2[tid] = l2b[tid];
        sw3[tid] = l3W[tid];
    }
    if (tid == 0) sb3[0] = l3b[0];
    for (int idx = tid; idx < 74 * 32; idx += 128) {
        int j = idx / 74, k = idx - j * 74;
        sW1[k * 32 + j] = l1W[idx];
    }
    for (int idx = tid; idx < 32 * 32; idx += 128) {
        int j = idx >> 5, k = idx & 31;
        sW2[k * 32 + j] = l2W[idx];
    }
    __syncthreads();

    for (int idx = tid; idx < 2048; idx += 128) {
        int r = idx >> 4, kq = (idx & 15) << 2;
        int row = base + r;
        float4 v = make_float4(0.f, 0.f, 0.f, 0.f);
        if (row < NN) {
            float di = g_dinv[row];
            float4 a = *(const float4*)&g_agg[row * 64 + kq];
            float4 s = *(const float4*)&state[row * 64 + kq];
            v.x = fmaxf(a.x * di + scb[kq + 0], 0.f) + s.x;
            v.y = fmaxf(a.y * di + scb[kq + 1], 0.f) + s.y;
            v.z = fmaxf(a.z * di + scb[kq + 2], 0.f) + s.z;
            v.w = fmaxf(a.w * di + scb[kq + 3], 0.f) + s.w;
        }
        sX[(kq + 0) * 132 + r] = v.x;
        sX[(kq + 1) * 132 + r] = v.y;
        sX[(kq + 2) * 132 + r] = v.z;
        sX[(kq + 3) * 132 + r] = v.w;
    }
    for (int idx = tid; idx < 128 * 10; idx += 128) {
        int r = idx / 10, k = idx - r * 10;
        int row = base + r;
        sX[(64 + k) * 132 + r] = (row < NN) ? g_xg[(row / ACTD) * 10 + k] : 0.f;
    }
    __syncthreads();

    int warp = tid >> 5, lane = tid & 31;
    int rg = lane >> 2, cg = lane & 3;
    int rowb = warp * 32 + rg * 4;
    int colb = cg * 8;

    ull acc[4][4];
#pragma unroll
    for (int r = 0; r < 4; r++)
#pragma unroll
        for (int c = 0; c < 4; c++) acc[r][c] = 0ull;
#pragma unroll 2
    for (int k = 0; k < 74; k++) {
        float4 xv = *(const float4*)&sX[k * 132 + rowb];
        ull xp[4] = {pk2(xv.x, xv.x), pk2(xv.y, xv.y), pk2(xv.z, xv.z), pk2(xv.w, xv.w)};
        const ulonglong2* wp = (const ulonglong2*)&sW1[k * 32 + colb];
        ulonglong2 wa = wp[0], wb = wp[1];
#pragma unroll
        for (int r = 0; r < 4; r++) {
            fma2(acc[r][0], xp[r], wa.x);
            fma2(acc[r][1], xp[r], wa.y);
            fma2(acc[r][2], xp[r], wb.x);
            fma2(acc[r][3], xp[r], wb.y);
        }
    }
    {
        float hv[4][8];
#pragma unroll
        for (int r = 0; r < 4; r++)
#pragma unroll
            for (int cp = 0; cp < 4; cp++) {
                float2 v = up2(acc[r][cp]);
                int c = colb + cp * 2;
                hv[r][cp * 2] = leakyf(v.x + sb1[c]);
                hv[r][cp * 2 + 1] = leakyf(v.y + sb1[c + 1]);
            }
#pragma unroll
        for (int c = 0; c < 8; c++) {
            float4 f = make_float4(hv[0][c], hv[1][c], hv[2][c], hv[3][c]);
            *(float4*)&sH[(colb + c) * 132 + rowb] = f;
        }
    }
    __syncthreads();

#pragma unroll
    for (int r = 0; r < 4; r++)
#pragma unroll
        for (int c = 0; c < 4; c++) acc[r][c] = 0ull;
#pragma unroll 4
    for (int k = 0; k < 32; k++) {
        float4 xv = *(const float4*)&sH[k * 132 + rowb];
        ull xp[4] = {pk2(xv.x, xv.x), pk2(xv.y, xv.y), pk2(xv.z, xv.z), pk2(xv.w, xv.w)};
        const ulonglong2* wp = (const ulonglong2*)&sW2[k * 32 + colb];
        ulonglong2 wa = wp[0], wb = wp[1];
#pragma unroll
        for (int r = 0; r < 4; r++) {
            fma2(acc[r][0], xp[r], wa.x);
            fma2(acc[r][1], xp[r], wa.y);
            fma2(acc[r][2], xp[r], wb.x);
            fma2(acc[r][3], xp[r], wb.y);
        }
    }

    float srow[4];
#pragma unroll
    for (int r = 0; r < 4; r++) {
        float s = 0.f;
#pragma unroll
        for (int cp = 0; cp < 4; cp++) {
            float2 v = up2(acc[r][cp]);
            int c = colb + cp * 2;
            float h0 = leakyf(v.x + sb2[c]);
            float h1 = leakyf(v.y + sb2[c + 1]);
            s += h0 * sw3[c] + h1 * sw3[c + 1];
        }
        srow[r] = s;
    }
#pragma unroll
    for (int r = 0; r < 4; r++) {
        srow[r] += __shfl_xor_sync(0xffffffffu, srow[r], 1);
        srow[r] += __shfl_xor_sync(0xffffffffu, srow[r], 2);
    }
    float lsum = 0.f;
    if (cg == 0) {
        float b3 = sb3[0];
#pragma unroll
        for (int r = 0; r < 4; r++) {
            int node = base + rowb + r;
            if (node < NN) {
                float conc = softplusf(srow[r] + b3);
                g_conc[node] = conc;
                lsum += conc;
            }
        }
    }
#pragma unroll
    for (int off = 16; off; off >>= 1) lsum += __shfl_xor_sync(0xffffffffu, lsum, off);
    if (lane == 0) atomicAdd(&g_sum, lsum);
}

// ---------------- finalize ----------------
__global__ void k_final(float* __restrict__ out, int writeReg) {
    int b = blockIdx.x * 256 + threadIdx.x;
    if (b == 0 && writeReg) out[NN] = g_sum * (1.0f / (float)NN);
    if (b >= BB) return;
    float c[ACTD];
    float s = 0.f;
#pragma unroll
    for (int a = 0; a < ACTD; a++) {
        c[a] = g_conc[b * ACTD + a];
        s += c[a];
    }
    float inv = 1.f / (s + 1e-20f);
#pragma unroll
    for (int a = 0; a < ACTD; a++) out[b * ACTD + a] = c[a] * inv;
}

// ---------------- launch ----------------
extern "C" void kernel_launch(void* const* d_in, const int* in_sizes, int n_in,
                              void* d_out, int out_size) {
    const float* state = (const float*)d_in[0];
    const void*  eidx  = d_in[1];
    const float* convW = (const float*)d_in[2];
    const float* convb = (const float*)d_in[3];
    const float* gW1   = (const float*)d_in[4];
    const float* gb1   = (const float*)d_in[5];
    const float* gW2   = (const float*)d_in[6];
    const float* gb2   = (const float*)d_in[7];
    const float* l1W   = (const float*)d_in[8];
    const float* l1b   = (const float*)d_in[9];
    const float* l2W   = (const float*)d_in[10];
    const float* l2b   = (const float*)d_in[11];
    const float* l3W   = (const float*)d_in[12];
    const float* l3b   = (const float*)d_in[13];
    float* out = (float*)d_out;

    cudaFuncSetAttribute(k_mega2, cudaFuncAttributeMaxDynamicSharedMemorySize, G3_SMEM);
    cudaFuncSetAttribute(k_mlp,  cudaFuncAttributeMaxDynamicSharedMemorySize, MLP_SMEM);

    k_wx<<<(4096 + GLB * KIN + BB * KIN / 8 + 255) / 256, 256>>>(gW1, state, convW);
    k_zero<<<(NN + 255) / 256, 256>>>(eidx);
    k_edges<<<(EE + 255) / 256, 256>>>(eidx);
    k_bsum<<<NSCAN_BLK, 1024>>>();
    k_bscan<<<1, 256>>>();
    k_off<<<NSCAN_BLK, 1024>>>();
    k_fill<<<(EE + 255) / 256, 256>>>();
    k_mega2<<<GLOB_BLKS + CONV_BLKS, 256, G3_SMEM>>>(gb1, gW2, gb2);
    k_gather<<<(NN * 32 + 255) / 256, 256>>>();
    k_mlp<<<(NN + 127) / 128, 128, MLP_SMEM>>>(state, convb, l1W, l1b, l2W, l2b, l3W, l3b);
    k_final<<<(BB + 255) / 256, 256>>>(out, out_size > NN ? 1 : 0);
}